// round 9
// baseline (speedup 1.0000x reference)
#include <cuda_runtime.h>
#include <cuda_bf16.h>
#include <math.h>

// pred/target: (32, 3, 512, 512) fp32 -> scalar fp32 mean |sobel(gray(p)) - sobel(gray(t))|
#define B      32
#define H      512
#define W      512
#define PLANE  (H * W)
#define IMG    (3 * PLANE)
#define NPIX   (B * PLANE)            // 8388608

#define RT     32                     // rows per CTA tile
#define TILESY (H / RT)               // 16
#define NBLK   (B * TILESY)           // 512
#define TPB    256
#define SROW   520                    // slot stride (floats); data at [4..515], zeros at 3/516

__device__ float        g_partials[NBLK];
__device__ unsigned int g_count = 0;

__device__ __forceinline__ float fsqrt_approx(float x) {
    float r; asm("sqrt.approx.f32 %0, %1;" : "=f"(r) : "f"(x)); return r;
}

// 3-channel float4 load for one row quad (zero-filled outside image).
__device__ __forceinline__ void ldg3(const float* __restrict__ img, int gy, int q,
                                     float4& r, float4& g, float4& bl)
{
    if ((unsigned)gy < (unsigned)H) {
        const float* p = img + (size_t)gy * W + 4 * q;
        r  = *(const float4*)p;
        g  = *(const float4*)(p + PLANE);
        bl = *(const float4*)(p + 2 * PLANE);
    } else {
        r = g = bl = make_float4(0.f, 0.f, 0.f, 0.f);
    }
}

__device__ __forceinline__ float4 gray4(float4 r, float4 g, float4 bl)
{
    float4 v;
    v.x = 0.299f * r.x + 0.587f * g.x + 0.114f * bl.x;
    v.y = 0.299f * r.y + 0.587f * g.y + 0.114f * bl.y;
    v.z = 0.299f * r.z + 0.587f * g.z + 0.114f * bl.z;
    v.w = 0.299f * r.w + 0.587f * g.w + 0.114f * bl.w;
    return v;
}

// Horizontal separable partials at column c of a ring slot.
__device__ __forceinline__ void rdrow(const float* __restrict__ base, int c,
                                      float& hx, float& hs)
{
    float l  = base[3 + c];
    float m  = base[4 + c];
    float rr = base[5 + c];
    hx = rr - l;                 // [-1, 0, 1]
    hs = l + 2.f * m + rr;       // [ 1, 2, 1]
}

__global__ __launch_bounds__(TPB, 3) void edge_loss_fused(
    const float* __restrict__ pred, const float* __restrict__ tgt,
    float* __restrict__ out)
{
    // 4-slot gray ring per image: [img][slot][SROW]  (16.6 KB). Row k lives in slot k&3.
    __shared__ float ring[2 * 4 * SROW];

    const int tile = blockIdx.x;
    const int b    = blockIdx.y;
    const int gy0  = tile * RT;
    const int tid  = threadIdx.x;

    // Staging role: thread stages quad q of image im.
    const int q  = tid & 127;
    const int im = tid >> 7;
    const float* simg = (im ? tgt : pred) + (size_t)b * IMG;
    float* myring = ring + im * 4 * SROW;

    // x-halo zeros for all 8 slots (never overwritten; STS writes only [4..515]).
    if (tid < 8) { ring[tid * SROW + 3] = 0.f; ring[tid * SROW + 516] = 0.f; }

    // ---- Prologue: rows -1 -> slot 3, 0 -> slot 0; prefetch rows 1 (A) and 2 (Bv) ----
    {
        float4 r, g, bl;
        ldg3(simg, gy0 - 1, q, r, g, bl);
        *(float4*)(myring + 3 * SROW + 4 + 4 * q) = gray4(r, g, bl);
        ldg3(simg, gy0, q, r, g, bl);
        *(float4*)(myring + 0 * SROW + 4 + 4 * q) = gray4(r, g, bl);
    }
    float4 Ar, Ag, Ab, Br, Bg, Bb;
    ldg3(simg, gy0 + 1, q, Ar, Ag, Ab);     // row 1, depth-2 slack
    ldg3(simg, gy0 + 2, q, Br, Bg, Bb);     // row 2
    __syncthreads();

    // ---- Init rolling windows from rows -1 (slot 3) and 0 (slot 0).
    //      Combos j: img = j>>1, col = (j&1) ? tid+256 : tid ----
    const int c0 = tid, c1 = tid + 256;
    float hx0[4], hx1[4], hs0[4], hs1[4];
    #pragma unroll
    for (int j = 0; j < 4; j++) {
        const float* base = ring + (j >> 1) * 4 * SROW;
        const int c = (j & 1) ? c1 : c0;
        rdrow(base + 3 * SROW, c, hx0[j], hs0[j]);   // row -1
        rdrow(base + 0 * SROW, c, hx1[j], hs1[j]);   // row  0
    }
    // No extra barrier needed: slot 3 is next written at iter 2 (row 3),
    // which is separated from these reads by two barriers.

    // ---- One pipeline step: STS(row r+1 from prefetch) -> LDG(row r+3) -> bar -> compute(r) ----
#define PSTEP(r, PR, PG, PB) do {                                            \
        const int s = ((r) + 1) & 3;                                         \
        *(float4*)(myring + s * SROW + 4 + 4 * q) = gray4(PR, PG, PB);       \
        if ((r) < RT - 2) ldg3(simg, gy0 + (r) + 3, q, PR, PG, PB);          \
        __syncthreads();                                                     \
        float mag[4];                                                        \
        _Pragma("unroll")                                                    \
        for (int j = 0; j < 4; j++) {                                        \
            const float* bnew = ring + (j >> 1) * 4 * SROW + s * SROW;       \
            const int c = (j & 1) ? c1 : c0;                                 \
            float hx2, hs2;                                                  \
            rdrow(bnew, c, hx2, hs2);                                        \
            float ex = hx0[j] + 2.f * hx1[j] + hx2;                          \
            float ey = hs2 - hs0[j];                                         \
            mag[j] = fsqrt_approx(ex * ex + ey * ey);                        \
            hx0[j] = hx1[j]; hx1[j] = hx2;                                   \
            hs0[j] = hs1[j]; hs1[j] = hs2;                                   \
        }                                                                    \
        acc += fabsf(mag[0] - mag[2]) + fabsf(mag[1] - mag[3]);              \
    } while (0)

    float acc = 0.f;
    #pragma unroll 1
    for (int rr = 0; rr < RT; rr += 2) {
        PSTEP(rr,     Ar, Ag, Ab);
        PSTEP(rr + 1, Br, Bg, Bb);
    }
#undef PSTEP

    // ---- Block reduction (fixed order) ----
    #pragma unroll
    for (int off = 16; off > 0; off >>= 1)
        acc += __shfl_down_sync(0xffffffffu, acc, off);

    __shared__ float wsum[8];
    __shared__ bool  isLast;
    const int lane = tid & 31, wid = tid >> 5;
    if (lane == 0) wsum[wid] = acc;
    __syncthreads();
    if (tid < 8) {
        float v = wsum[tid];
        #pragma unroll
        for (int off = 4; off > 0; off >>= 1)
            v += __shfl_down_sync(0x000000ffu, v, off);
        if (tid == 0) {
            g_partials[b * TILESY + tile] = v;
            __threadfence();
            unsigned int old = atomicAdd(&g_count, 1u);
            isLast = (old == (unsigned)(NBLK - 1));
        }
    }
    __syncthreads();

    // ---- Fused deterministic final reduction (last block, fp64 fixed order) ----
    if (isLast) {
        __shared__ double ds[TPB];
        double a = 0.0;
        #pragma unroll
        for (int i = 0; i < NBLK / TPB; i++)
            a += (double)__ldcg(&g_partials[tid + i * TPB]);
        ds[tid] = a;
        __syncthreads();
        #pragma unroll
        for (int st = TPB / 2; st > 0; st >>= 1) {
            if (tid < st) ds[tid] += ds[tid + st];
            __syncthreads();
        }
        if (tid == 0) {
            out[0] = (float)(ds[0] / (double)NPIX);
            g_count = 0;   // self-reset for graph replay
        }
    }
}

extern "C" void kernel_launch(void* const* d_in, const int* in_sizes, int n_in,
                              void* d_out, int out_size)
{
    const float* pred = (const float*)d_in[0];
    const float* tgt  = (const float*)d_in[1];
    float* out = (float*)d_out;

    dim3 grid(TILESY, B);   // (16, 32) = 512 blocks
    edge_loss_fused<<<grid, TPB>>>(pred, tgt, out);
}

// round 10
// speedup vs baseline: 1.1972x; 1.1972x over previous
#include <cuda_runtime.h>
#include <cuda_bf16.h>
#include <math.h>

// pred/target: (32, 3, 512, 512) fp32 -> scalar fp32 mean |sobel(gray(p)) - sobel(gray(t))|
#define B      32
#define H      512
#define W      512
#define PLANE  (H * W)
#define IMG    (3 * PLANE)
#define NPIX   (B * PLANE)            // 8388608

#define RT     32                     // rows per CTA tile
#define TILESY (H / RT)               // 16
#define STRIPS 2                      // 256-col strips
#define SW     256
#define NBLK   (B * TILESY * STRIPS)  // 1024
#define TPB    128                    // 4 warps
#define SROW   264                    // slot stride (floats): halo_l@3, data 4..259, halo_r@260

__device__ float        g_partials[NBLK];
__device__ unsigned int g_count = 0;

__device__ __forceinline__ float fsqrt_approx(float x) {
    float r; asm("sqrt.approx.f32 %0, %1;" : "=f"(r) : "f"(x)); return r;
}

// 3-channel float4 load of one quad (zero outside image rows).
__device__ __forceinline__ void ldg3(const float* __restrict__ img, int gy, int goff,
                                     float4& r, float4& g, float4& bl)
{
    if ((unsigned)gy < (unsigned)H) {
        const float* p = img + (size_t)gy * W + goff;
        r  = *(const float4*)p;
        g  = *(const float4*)(p + PLANE);
        bl = *(const float4*)(p + 2 * PLANE);
    } else {
        r = g = bl = make_float4(0.f, 0.f, 0.f, 0.f);
    }
}

__device__ __forceinline__ float4 gray4(float4 r, float4 g, float4 bl)
{
    float4 v;
    v.x = 0.299f * r.x + 0.587f * g.x + 0.114f * bl.x;
    v.y = 0.299f * r.y + 0.587f * g.y + 0.114f * bl.y;
    v.z = 0.299f * r.z + 0.587f * g.z + 0.114f * bl.z;
    v.w = 0.299f * r.w + 0.587f * g.w + 0.114f * bl.w;
    return v;
}

// Horizontal separable partials at local column c (0..255) of a ring slot.
__device__ __forceinline__ void rdrow(const float* __restrict__ base, int c,
                                      float& hx, float& hs)
{
    float l  = base[3 + c];
    float m  = base[4 + c];
    float rr = base[5 + c];
    hx = rr - l;                 // [-1, 0, 1]
    hs = l + 2.f * m + rr;       // [ 1, 2, 1]
}

__global__ __launch_bounds__(TPB, 8) void edge_loss_fused(
    const float* __restrict__ pred, const float* __restrict__ tgt,
    float* __restrict__ out)
{
    // Ring: [img][slot][SROW]  (4.2 KB)
    __shared__ float ring[2 * 2 * SROW];

    const int tid   = threadIdx.x;
    const int strip = blockIdx.x & (STRIPS - 1);
    const int tile  = blockIdx.x >> 1;
    const int b     = blockIdx.y;
    const int gy0   = tile * RT;
    const int gx0   = strip * SW;

    const float* pr = pred + (size_t)b * IMG;
    const float* tr = tgt  + (size_t)b * IMG;

    // Staging role: thread stages quad q (4 cols) of image im.
    const int q  = tid & 63;
    const int im = tid >> 6;
    const float* simg = im ? tr : pr;
    float* myring = ring + im * 2 * SROW;
    const int goff = gx0 + 4 * q;

    // Edge roles (tid 0..3): load single boundary gray pixel per img per side.
    const bool isE    = (tid < 4);
    const int  eimg   = tid & 1;
    const bool eleft  = (tid < 2);
    const int  ecol   = eleft ? (gx0 - 1) : (gx0 + SW);
    const bool evalid = eleft ? (strip > 0) : (strip < STRIPS - 1);
    const float* ep   = eimg ? tr : pr;
    float* ering      = ring + eimg * 2 * SROW;
    const int  eoffs  = eleft ? 3 : 260;

    float4 fr, fg, fb;          // prefetched rgb quad
    float  er = 0.f, eg = 0.f, eb = 0.f;   // prefetched edge rgb

#define LDROW(gy) do {                                                       \
        ldg3(simg, (gy), goff, fr, fg, fb);                                  \
        if (isE) {                                                           \
            if (evalid && (unsigned)(gy) < (unsigned)H) {                    \
                const int eo = (gy) * W + ecol;                              \
                er = ep[eo]; eg = ep[eo + PLANE]; eb = ep[eo + 2 * PLANE];   \
            } else { er = eg = eb = 0.f; }                                   \
        }                                                                    \
    } while (0)

#define STROW(slot) do {                                                     \
        *(float4*)(myring + (slot) * SROW + 4 + 4 * q) = gray4(fr, fg, fb);  \
        if (isE)                                                             \
            ering[(slot) * SROW + eoffs] = 0.299f * er + 0.587f * eg + 0.114f * eb; \
    } while (0)

    // ---- Prologue: rows gy0-1 -> slot1, gy0 -> slot0; prefetch gy0+1 ----
    LDROW(gy0 - 1);  STROW(1);
    LDROW(gy0);      STROW(0);
    LDROW(gy0 + 1);
    __syncthreads();

    // ---- Init rolling windows. Combos j: img = j>>1, col = (j&1) ? tid+128 : tid ----
    const int c0 = tid, c1 = tid + 128;
    float hx0[4], hx1[4], hs0[4], hs1[4];
    #pragma unroll
    for (int j = 0; j < 4; j++) {
        const float* base = ring + (j >> 1) * 2 * SROW;
        const int c = (j & 1) ? c1 : c0;
        rdrow(base + 1 * SROW, c, hx0[j], hs0[j]);   // row -1 (slot 1)
        rdrow(base + 0 * SROW, c, hx1[j], hs1[j]);   // row  0 (slot 0)
    }
    __syncthreads();   // reads of slot1 done before iter 0 overwrites it

    // ---- Pipelined mainloop: STS(r+1) -> LDG(r+2) -> bar -> compute(r) ----
    float acc = 0.f;
    #pragma unroll 2
    for (int r = 0; r < RT; r++) {
        const int s = (r + 1) & 1;
        STROW(s);
        if (r < RT - 1) LDROW(gy0 + r + 2);
        __syncthreads();

        float mag[4];
        #pragma unroll
        for (int j = 0; j < 4; j++) {
            const float* bnew = ring + (j >> 1) * 2 * SROW + s * SROW;
            const int c = (j & 1) ? c1 : c0;
            float hx2, hs2;
            rdrow(bnew, c, hx2, hs2);
            float ex = hx0[j] + 2.f * hx1[j] + hx2;
            float ey = hs2 - hs0[j];
            mag[j] = fsqrt_approx(ex * ex + ey * ey);
            hx0[j] = hx1[j]; hx1[j] = hx2;
            hs0[j] = hs1[j]; hs1[j] = hs2;
        }
        acc += fabsf(mag[0] - mag[2]) + fabsf(mag[1] - mag[3]);
    }
#undef LDROW
#undef STROW

    // ---- Block reduction (fixed order, 4 warps) ----
    #pragma unroll
    for (int off = 16; off > 0; off >>= 1)
        acc += __shfl_down_sync(0xffffffffu, acc, off);

    __shared__ float wsum[4];
    __shared__ bool  isLast;
    const int lane = tid & 31, wid = tid >> 5;
    if (lane == 0) wsum[wid] = acc;
    __syncthreads();
    if (tid < 4) {
        float v = wsum[tid];
        v += __shfl_down_sync(0x0000000fu, v, 2);
        v += __shfl_down_sync(0x0000000fu, v, 1);
        if (tid == 0) {
            g_partials[b * (TILESY * STRIPS) + blockIdx.x] = v;
            __threadfence();
            unsigned int old = atomicAdd(&g_count, 1u);
            isLast = (old == (unsigned)(NBLK - 1));
        }
    }
    __syncthreads();

    // ---- Fused deterministic final reduction (last block, fp64 fixed order) ----
    if (isLast) {
        __shared__ double ds[TPB];
        double a = 0.0;
        #pragma unroll
        for (int i = 0; i < NBLK / TPB; i++)
            a += (double)__ldcg(&g_partials[tid + i * TPB]);
        ds[tid] = a;
        __syncthreads();
        #pragma unroll
        for (int st = TPB / 2; st > 0; st >>= 1) {
            if (tid < st) ds[tid] += ds[tid + st];
            __syncthreads();
        }
        if (tid == 0) {
            out[0] = (float)(ds[0] / (double)NPIX);
            g_count = 0;   // self-reset for graph replay
        }
    }
}

extern "C" void kernel_launch(void* const* d_in, const int* in_sizes, int n_in,
                              void* d_out, int out_size)
{
    const float* pred = (const float*)d_in[0];
    const float* tgt  = (const float*)d_in[1];
    float* out = (float*)d_out;

    dim3 grid(TILESY * STRIPS, B);   // (32, 32) = 1024 blocks, fully resident at 8/SM
    edge_loss_fused<<<grid, TPB>>>(pred, tgt, out);
}